// round 2
// baseline (speedup 1.0000x reference)
#include <cuda_runtime.h>

#define MAXN 4096
#define IMG_W 128
#define IMG_H 128
#define FXc 300.0f
#define FYc 300.0f

// ---- scratch (allocation-free per harness rules) ----
__device__ float  g_z[MAXN];
__device__ float4 g_a[MAXN], g_b[MAXN], g_c[MAXN];   // unsorted payload
__device__ float4 s_a[MAXN], s_b[MAXN], s_c[MAXN];   // depth-sorted payload

// SH constants
__device__ __constant__ float C0 = 0.28209479177387814f;
__device__ __constant__ float C1 = 0.4886025119029199f;
__device__ __constant__ float C2_[5] = {1.0925484305920792f, -1.0925484305920792f,
                                        0.31539156525252005f, -1.0925484305920792f,
                                        0.5462742152960396f};
__device__ __constant__ float C3_[7] = {-0.5900435899266435f, 2.890611442640554f,
                                        -0.4570457994644658f, 0.3731763325901154f,
                                        -0.4570457994644658f, 1.445305721320277f,
                                        -0.5900435899266435f};

__global__ void preprocess_kernel(const float* __restrict__ pw,
                                  const float* __restrict__ lowsh,
                                  const float* __restrict__ highsh,
                                  const float* __restrict__ rawop,
                                  const float* __restrict__ sraw,
                                  const float* __restrict__ rraw,
                                  const float* __restrict__ Rcw,
                                  const float* __restrict__ tcw,
                                  int n) {
    int i = blockIdx.x * blockDim.x + threadIdx.x;
    if (i >= n) return;

    float R00=Rcw[0],R01=Rcw[1],R02=Rcw[2];
    float R10=Rcw[3],R11=Rcw[4],R12=Rcw[5];
    float R20=Rcw[6],R21=Rcw[7],R22=Rcw[8];
    float t0=tcw[0], t1=tcw[1], t2=tcw[2];

    float px = pw[i*3+0], py = pw[i*3+1], pz = pw[i*3+2];

    // camera-space point
    float pc0 = R00*px + R01*py + R02*pz + t0;
    float pc1 = R10*px + R11*py + R12*pz + t1;
    float pc2 = R20*px + R21*py + R22*pz + t2;
    float invz = 1.0f / pc2;
    float u = FXc * pc0 * invz + 0.5f * IMG_W;
    float v = FYc * pc1 * invz + 0.5f * IMG_H;

    // opacity
    float op = 1.0f / (1.0f + expf(-rawop[i]));

    // scales
    float s0 = expf(sraw[i*3+0]);
    float s1 = expf(sraw[i*3+1]);
    float s2 = expf(sraw[i*3+2]);

    // normalized quaternion (w,x,y,z)
    float qw = rraw[i*4+0], qx = rraw[i*4+1], qy = rraw[i*4+2], qz = rraw[i*4+3];
    float qn = rsqrtf(qw*qw + qx*qx + qy*qy + qz*qz);
    qw *= qn; qx *= qn; qy *= qn; qz *= qn;

    float Rg00 = 1.0f - 2.0f*(qy*qy + qz*qz);
    float Rg01 = 2.0f*(qx*qy - qw*qz);
    float Rg02 = 2.0f*(qx*qz + qw*qy);
    float Rg10 = 2.0f*(qx*qy + qw*qz);
    float Rg11 = 1.0f - 2.0f*(qx*qx + qz*qz);
    float Rg12 = 2.0f*(qy*qz - qw*qx);
    float Rg20 = 2.0f*(qx*qz - qw*qy);
    float Rg21 = 2.0f*(qy*qz + qw*qx);
    float Rg22 = 1.0f - 2.0f*(qx*qx + qy*qy);

    // M = Rg * diag(s)  (column scaling)
    float M00 = Rg00*s0, M01 = Rg01*s1, M02 = Rg02*s2;
    float M10 = Rg10*s0, M11 = Rg11*s1, M12 = Rg12*s2;
    float M20 = Rg20*s0, M21 = Rg21*s1, M22 = Rg22*s2;

    // J (2x3 nonzeros) ; T = J @ Rcw
    float j00 = FXc*invz, j02 = -FXc*pc0*invz*invz;
    float j11 = FYc*invz, j12 = -FYc*pc1*invz*invz;
    float T00 = j00*R00 + j02*R20;
    float T01 = j00*R01 + j02*R21;
    float T02 = j00*R02 + j02*R22;
    float T10 = j11*R10 + j12*R20;
    float T11 = j11*R11 + j12*R21;
    float T12 = j11*R12 + j12*R22;

    // V = T @ M (2x3); cov2d = V V^T
    float V00 = T00*M00 + T01*M10 + T02*M20;
    float V01 = T00*M01 + T01*M11 + T02*M21;
    float V02 = T00*M02 + T01*M12 + T02*M22;
    float V10 = T10*M00 + T11*M10 + T12*M20;
    float V11 = T10*M01 + T11*M11 + T12*M21;
    float V12 = T10*M02 + T11*M12 + T12*M22;

    float a  = V00*V00 + V01*V01 + V02*V02 + 0.3f;
    float b  = V00*V10 + V01*V11 + V02*V12;
    float cc = V10*V10 + V11*V11 + V12*V12 + 0.3f;
    float det = a*cc - b*b;
    float ia =  cc / det;
    float ib = -b  / det;
    float ic =  a  / det;

    // view dir: dirs = pw - twc,  twc = -(Rcw^T @ tcw)
    float dx0 = px + (R00*t0 + R10*t1 + R20*t2);
    float dy0 = py + (R01*t0 + R11*t1 + R21*t2);
    float dz0 = pz + (R02*t0 + R12*t1 + R22*t2);
    float dn = rsqrtf(dx0*dx0 + dy0*dy0 + dz0*dz0);
    float x = dx0*dn, y = dy0*dn, z = dz0*dn;

    float xx = x*x, yy = y*y, zz = z*z;
    float xy = x*y, yz = y*z, xz = x*z;

    // SH basis values (shared across channels)
    float b1m = -C1*y, b1z = C1*z, b1x = -C1*x;
    float b4 = C2_[0]*xy;
    float b5 = C2_[1]*yz;
    float b6 = C2_[2]*(2.0f*zz - xx - yy);
    float b7 = C2_[3]*xz;
    float b8 = C2_[4]*(xx - yy);
    float b9  = C3_[0]*y*(3.0f*xx - yy);
    float b10 = C3_[1]*xy*z;
    float b11 = C3_[2]*y*(4.0f*zz - xx - yy);
    float b12 = C3_[3]*z*(2.0f*zz - 3.0f*xx - 3.0f*yy);
    float b13 = C3_[4]*x*(4.0f*zz - xx - yy);
    float b14 = C3_[5]*z*(xx - yy);
    float b15 = C3_[6]*x*(xx - 3.0f*yy);

    float col[3];
    const float* hs = highsh + i*45;
    #pragma unroll
    for (int ch = 0; ch < 3; ch++) {
        float res = C0 * lowsh[i*3+ch];
        res += b1m * hs[0*3+ch] + b1z * hs[1*3+ch] + b1x * hs[2*3+ch];
        res += b4  * hs[3*3+ch] + b5  * hs[4*3+ch] + b6  * hs[5*3+ch]
             + b7  * hs[6*3+ch] + b8  * hs[7*3+ch];
        res += b9  * hs[8*3+ch] + b10 * hs[9*3+ch] + b11 * hs[10*3+ch]
             + b12 * hs[11*3+ch] + b13 * hs[12*3+ch] + b14 * hs[13*3+ch]
             + b15 * hs[14*3+ch];
        col[ch] = fmaxf(res + 0.5f, 0.0f);
    }

    float valid = (pc2 > 0.2f) ? 1.0f : 0.0f;

    g_z[i] = pc2;
    g_a[i] = make_float4(u, v, ia, ib);
    g_b[i] = make_float4(ic, op, col[0], col[1]);
    g_c[i] = make_float4(col[2], valid, 0.0f, 0.0f);
}

// stable rank-sort by z (ascending), scatter payload into sorted arrays
__global__ void sort_scatter_kernel(int n) {
    __shared__ float sz[MAXN];
    for (int j = threadIdx.x; j < n; j += blockDim.x) sz[j] = g_z[j];
    __syncthreads();
    int i = blockIdx.x * blockDim.x + threadIdx.x;
    if (i >= n) return;
    float zi = sz[i];
    int rank = 0;
    for (int j = 0; j < n; j++) {
        float zj = sz[j];
        rank += (zj < zi) || (zj == zi && j < i);
    }
    s_a[rank] = g_a[i];
    s_b[rank] = g_b[i];
    s_c[rank] = g_c[i];
}

#define CHUNK 64

__global__ void __launch_bounds__(CHUNK) render_kernel(float* __restrict__ out, int n) {
    __shared__ float4 ca[CHUNK], cb[CHUNK], cc[CHUNK];

    int t  = threadIdx.x;
    int tx = t & 7, ty = t >> 3;
    int pxi = blockIdx.x * 8 + tx;
    int pyi = blockIdx.y * 8 + ty;
    float pxf = pxi + 0.5f;
    float pyf = pyi + 0.5f;

    float T = 1.0f, cr = 0.0f, cg = 0.0f, cbl = 0.0f;

    for (int base = 0; base < n; base += CHUNK) {
        // doubles as the barrier protecting smem reuse
        if (__syncthreads_and(T < 1e-5f)) break;
        int idx = base + t;
        if (idx < n) {
            ca[t] = s_a[idx];
            cb[t] = s_b[idx];
            cc[t] = s_c[idx];
        }
        __syncthreads();
        int m = min(CHUNK, n - base);
        for (int k = 0; k < m; k++) {
            float4 A = ca[k];
            float4 B = cb[k];
            float dx = A.x - pxf;
            float dy = A.y - pyf;
            float power = -0.5f * (A.z * dx * dx + B.x * dy * dy) - A.w * dx * dy;
            float gw = __expf(fminf(power, 0.0f));
            float alpha = fminf(0.99f, B.y * gw);
            if (alpha >= (1.0f / 255.0f)) {
                float4 C = cc[k];
                alpha *= C.y;                 // valid mask
                float w = T * alpha;
                cr  += w * B.z;
                cg  += w * B.w;
                cbl += w * C.x;
                T *= (1.0f - alpha);
            }
        }
    }

    int o = (pyi * IMG_W + pxi) * 3;
    out[o + 0] = cr;
    out[o + 1] = cg;
    out[o + 2] = cbl;
}

extern "C" void kernel_launch(void* const* d_in, const int* in_sizes, int n_in,
                              void* d_out, int out_size) {
    const float* pw     = (const float*)d_in[0];
    const float* lowsh  = (const float*)d_in[1];
    const float* highsh = (const float*)d_in[2];
    const float* rawop  = (const float*)d_in[3];
    const float* sraw   = (const float*)d_in[4];
    const float* rraw   = (const float*)d_in[5];
    const float* Rcw    = (const float*)d_in[6];
    const float* tcw    = (const float*)d_in[7];
    int n = in_sizes[0] / 3;

    preprocess_kernel<<<(n + 127) / 128, 128>>>(pw, lowsh, highsh, rawop, sraw, rraw, Rcw, tcw, n);
    sort_scatter_kernel<<<(n + 255) / 256, 256>>>(n);
    render_kernel<<<dim3(IMG_W / 8, IMG_H / 8), CHUNK>>>((float*)d_out, n);
}

// round 4
// speedup vs baseline: 2.0006x; 2.0006x over previous
#include <cuda_runtime.h>

#define MAXN 4096
#define IMG_W 128
#define IMG_H 128
#define TILE 8
#define TILES_X (IMG_W / TILE)
#define TILES_Y (IMG_H / TILE)
#define NTILES (TILES_X * TILES_Y)
#define FXc 300.0f
#define FYc 300.0f
#define LOG2E 1.4426950408889634f

// ---- scratch (allocation-free per harness rules) ----
__device__ float  g_z[MAXN];
__device__ float4 g_a[MAXN], g_b[MAXN];
__device__ float2 g_c[MAXN];
__device__ float4 s_a[MAXN], s_b[MAXN];       // depth-sorted payload
__device__ float2 s_c[MAXN];                  // (colB, rmax2)
__device__ unsigned short g_tile_list[NTILES * MAXN];
__device__ int g_tile_count[NTILES];

__device__ __constant__ float C0 = 0.28209479177387814f;
__device__ __constant__ float C1 = 0.4886025119029199f;
__device__ __constant__ float C2_[5] = {1.0925484305920792f, -1.0925484305920792f,
                                        0.31539156525252005f, -1.0925484305920792f,
                                        0.5462742152960396f};
__device__ __constant__ float C3_[7] = {-0.5900435899266435f, 2.890611442640554f,
                                        -0.4570457994644658f, 0.3731763325901154f,
                                        -0.4570457994644658f, 1.445305721320277f,
                                        -0.5900435899266435f};

__global__ void preprocess_kernel(const float* __restrict__ pw,
                                  const float* __restrict__ lowsh,
                                  const float* __restrict__ highsh,
                                  const float* __restrict__ rawop,
                                  const float* __restrict__ sraw,
                                  const float* __restrict__ rraw,
                                  const float* __restrict__ Rcw,
                                  const float* __restrict__ tcw,
                                  int n) {
    int i = blockIdx.x * blockDim.x + threadIdx.x;
    if (i >= n) return;

    float R00=Rcw[0],R01=Rcw[1],R02=Rcw[2];
    float R10=Rcw[3],R11=Rcw[4],R12=Rcw[5];
    float R20=Rcw[6],R21=Rcw[7],R22=Rcw[8];
    float t0=tcw[0], t1=tcw[1], t2=tcw[2];

    float px = pw[i*3+0], py = pw[i*3+1], pz = pw[i*3+2];

    float pc0 = R00*px + R01*py + R02*pz + t0;
    float pc1 = R10*px + R11*py + R12*pz + t1;
    float pc2 = R20*px + R21*py + R22*pz + t2;
    float invz = 1.0f / pc2;
    float u = FXc * pc0 * invz + 0.5f * IMG_W;
    float v = FYc * pc1 * invz + 0.5f * IMG_H;

    float op = 1.0f / (1.0f + expf(-rawop[i]));

    float s0 = expf(sraw[i*3+0]);
    float s1 = expf(sraw[i*3+1]);
    float s2 = expf(sraw[i*3+2]);

    float qw = rraw[i*4+0], qx = rraw[i*4+1], qy = rraw[i*4+2], qz = rraw[i*4+3];
    float qn = rsqrtf(qw*qw + qx*qx + qy*qy + qz*qz);
    qw *= qn; qx *= qn; qy *= qn; qz *= qn;

    float Rg00 = 1.0f - 2.0f*(qy*qy + qz*qz);
    float Rg01 = 2.0f*(qx*qy - qw*qz);
    float Rg02 = 2.0f*(qx*qz + qw*qy);
    float Rg10 = 2.0f*(qx*qy + qw*qz);
    float Rg11 = 1.0f - 2.0f*(qx*qx + qz*qz);
    float Rg12 = 2.0f*(qy*qz - qw*qx);
    float Rg20 = 2.0f*(qx*qz - qw*qy);
    float Rg21 = 2.0f*(qy*qz + qw*qx);
    float Rg22 = 1.0f - 2.0f*(qx*qx + qy*qy);

    float M00 = Rg00*s0, M01 = Rg01*s1, M02 = Rg02*s2;
    float M10 = Rg10*s0, M11 = Rg11*s1, M12 = Rg12*s2;
    float M20 = Rg20*s0, M21 = Rg21*s1, M22 = Rg22*s2;

    float j00 = FXc*invz, j02 = -FXc*pc0*invz*invz;
    float j11 = FYc*invz, j12 = -FYc*pc1*invz*invz;
    float T00 = j00*R00 + j02*R20;
    float T01 = j00*R01 + j02*R21;
    float T02 = j00*R02 + j02*R22;
    float T10 = j11*R10 + j12*R20;
    float T11 = j11*R11 + j12*R21;
    float T12 = j11*R12 + j12*R22;

    float V00 = T00*M00 + T01*M10 + T02*M20;
    float V01 = T00*M01 + T01*M11 + T02*M21;
    float V02 = T00*M02 + T01*M12 + T02*M22;
    float V10 = T10*M00 + T11*M10 + T12*M20;
    float V11 = T10*M01 + T11*M11 + T12*M21;
    float V12 = T10*M02 + T11*M12 + T12*M22;

    float a  = V00*V00 + V01*V01 + V02*V02 + 0.3f;
    float b  = V00*V10 + V01*V11 + V02*V12;
    float cc = V10*V10 + V11*V11 + V12*V12 + 0.3f;
    float det = a*cc - b*b;
    float ia =  cc / det;
    float ib = -b  / det;
    float ic =  a  / det;

    // view dir
    float dx0 = px + (R00*t0 + R10*t1 + R20*t2);
    float dy0 = py + (R01*t0 + R11*t1 + R21*t2);
    float dz0 = pz + (R02*t0 + R12*t1 + R22*t2);
    float dn = rsqrtf(dx0*dx0 + dy0*dy0 + dz0*dz0);
    float x = dx0*dn, y = dy0*dn, z = dz0*dn;

    float xx = x*x, yy = y*y, zz = z*z;
    float xy = x*y, yz = y*z, xz = x*z;

    float b1m = -C1*y, b1z = C1*z, b1x = -C1*x;
    float b4 = C2_[0]*xy;
    float b5 = C2_[1]*yz;
    float b6 = C2_[2]*(2.0f*zz - xx - yy);
    float b7 = C2_[3]*xz;
    float b8 = C2_[4]*(xx - yy);
    float b9  = C3_[0]*y*(3.0f*xx - yy);
    float b10 = C3_[1]*xy*z;
    float b11 = C3_[2]*y*(4.0f*zz - xx - yy);
    float b12 = C3_[3]*z*(2.0f*zz - 3.0f*xx - 3.0f*yy);
    float b13 = C3_[4]*x*(4.0f*zz - xx - yy);
    float b14 = C3_[5]*z*(xx - yy);
    float b15 = C3_[6]*x*(xx - 3.0f*yy);

    float col[3];
    const float* hs = highsh + i*45;
    #pragma unroll
    for (int ch = 0; ch < 3; ch++) {
        float res = C0 * lowsh[i*3+ch];
        res += b1m * hs[0*3+ch] + b1z * hs[1*3+ch] + b1x * hs[2*3+ch];
        res += b4  * hs[3*3+ch] + b5  * hs[4*3+ch] + b6  * hs[5*3+ch]
             + b7  * hs[6*3+ch] + b8  * hs[7*3+ch];
        res += b9  * hs[8*3+ch] + b10 * hs[9*3+ch] + b11 * hs[10*3+ch]
             + b12 * hs[11*3+ch] + b13 * hs[12*3+ch] + b14 * hs[13*3+ch]
             + b15 * hs[14*3+ch];
        col[ch] = fmaxf(res + 0.5f, 0.0f);
    }

    // fold valid into opacity (identical blending result)
    float op_eff = (pc2 > 0.2f) ? op : 0.0f;

    // conic coefficients pre-scaled so power*log2(e) = A2*dx^2 + C2*dy^2 + B2*dx*dy
    float A2 = -0.5f * ia * LOG2E;
    float B2 = -ib * LOG2E;
    float Cc2 = -0.5f * ic * LOG2E;

    // conservative cull radius: alpha = op*exp(power) < 1/255 guaranteed when
    // d^2 > 2*ln(255*op)*lambda_max(Sigma2d)
    float mid = 0.5f * (a + cc);
    float disc = sqrtf(0.25f * (a - cc) * (a - cc) + b * b);
    float lmax = mid + disc;
    float t255 = 255.0f * op_eff;
    float r2 = (t255 > 1.0f) ? 2.0f * logf(t255) * lmax * 1.0002f : -1.0f;

    g_z[i] = pc2;
    g_a[i] = make_float4(u, v, A2, B2);
    g_b[i] = make_float4(Cc2, op_eff, col[0], col[1]);
    g_c[i] = make_float2(col[2], r2);
}

// stable rank-sort by z (ascending), scatter payload into sorted arrays
__global__ void sort_scatter_kernel(int n) {
    __shared__ float sz[MAXN];
    for (int j = threadIdx.x; j < n; j += blockDim.x) sz[j] = g_z[j];
    __syncthreads();
    int i = blockIdx.x * blockDim.x + threadIdx.x;
    if (i >= n) return;
    float zi = sz[i];
    int rank = 0;
    for (int j = 0; j < n; j++) {
        float zj = sz[j];
        rank += (zj < zi) || (zj == zi && j < i);
    }
    s_a[rank] = g_a[i];
    s_b[rank] = g_b[i];
    s_c[rank] = g_c[i];
}

// per-tile binning: one block per 8x8 tile, stable order-preserving compaction
__global__ void __launch_bounds__(256) bin_kernel(int n) {
    int b = blockIdx.x;
    int tlx = b & (TILES_X - 1);
    int tly = b >> 4;               // TILES_X == 16
    float xlo = tlx * TILE + 0.5f, xhi = tlx * TILE + (TILE - 0.5f);
    float ylo = tly * TILE + 0.5f, yhi = tly * TILE + (TILE - 0.5f);

    int t = threadIdx.x;
    int wid = t >> 5, lid = t & 31;

    __shared__ int sbase;
    __shared__ int wtot[8], woff[8];
    __shared__ int ctot;
    if (t == 0) sbase = 0;
    __syncthreads();

    unsigned short* lst = g_tile_list + b * MAXN;

    for (int chunk = 0; chunk < n; chunk += 256) {
        int i = chunk + t;
        int pred = 0;
        if (i < n) {
            float4 A = s_a[i];
            float r2 = s_c[i].y;
            float cu = fminf(fmaxf(A.x, xlo), xhi);
            float cv = fminf(fmaxf(A.y, ylo), yhi);
            float ddx = A.x - cu, ddy = A.y - cv;
            pred = (ddx * ddx + ddy * ddy <= r2) ? 1 : 0;
        }
        unsigned m = __ballot_sync(0xffffffffu, pred);
        int wrank = __popc(m & ((1u << lid) - 1u));
        if (lid == 0) wtot[wid] = __popc(m);
        __syncthreads();
        if (t == 0) {
            int s = 0;
            #pragma unroll
            for (int w = 0; w < 8; w++) { woff[w] = s; s += wtot[w]; }
            ctot = s;
        }
        __syncthreads();
        if (pred) lst[sbase + woff[wid] + wrank] = (unsigned short)i;
        __syncthreads();
        if (t == 0) sbase += ctot;
        __syncthreads();
    }
    if (t == 0) g_tile_count[b] = sbase;
}

#define CHUNK 64

__global__ void __launch_bounds__(CHUNK) render_kernel(float* __restrict__ out) {
    __shared__ float4 ca[CHUNK], cb[CHUNK];
    __shared__ float  ccb[CHUNK];

    int t  = threadIdx.x;
    int tx = t & 7, ty = t >> 3;
    int pxi = blockIdx.x * TILE + tx;
    int pyi = blockIdx.y * TILE + ty;
    float pxf = pxi + 0.5f;
    float pyf = pyi + 0.5f;

    int b = blockIdx.y * TILES_X + blockIdx.x;
    int count = g_tile_count[b];
    const unsigned short* lst = g_tile_list + b * MAXN;

    float T = 1.0f, cr = 0.0f, cg = 0.0f, cbl = 0.0f;

    for (int base = 0; base < count; base += CHUNK) {
        // doubles as the barrier protecting smem reuse
        if (__syncthreads_and(T < 1e-5f)) break;
        if (base + t < count) {
            int idx = lst[base + t];
            ca[t]  = s_a[idx];
            cb[t]  = s_b[idx];
            ccb[t] = s_c[idx].x;
        }
        __syncthreads();
        int m = min(CHUNK, count - base);
        #pragma unroll 4
        for (int k = 0; k < m; k++) {
            float4 A = ca[k];
            float4 B = cb[k];
            float dx = A.x - pxf;
            float dy = A.y - pyf;
            // power in log2 domain: 3 FMA
            float p = A.z * dx * dx;
            p = fmaf(B.x, dy * dy, p);
            p = fmaf(A.w, dx * dy, p);
            p = fminf(p, 0.0f);
            float gw;
            asm("ex2.approx.f32 %0, %1;" : "=f"(gw) : "f"(p));
            float alpha = fminf(0.99f, B.y * gw);
            alpha = (alpha >= (1.0f / 255.0f)) ? alpha : 0.0f;
            float w = T * alpha;
            cr  = fmaf(w, B.z, cr);
            cg  = fmaf(w, B.w, cg);
            cbl = fmaf(w, ccb[k], cbl);
            T = fmaf(-alpha, T, T);
        }
    }

    int o = (pyi * IMG_W + pxi) * 3;
    out[o + 0] = cr;
    out[o + 1] = cg;
    out[o + 2] = cbl;
}

extern "C" void kernel_launch(void* const* d_in, const int* in_sizes, int n_in,
                              void* d_out, int out_size) {
    const float* pw     = (const float*)d_in[0];
    const float* lowsh  = (const float*)d_in[1];
    const float* highsh = (const float*)d_in[2];
    const float* rawop  = (const float*)d_in[3];
    const float* sraw   = (const float*)d_in[4];
    const float* rraw   = (const float*)d_in[5];
    const float* Rcw    = (const float*)d_in[6];
    const float* tcw    = (const float*)d_in[7];
    int n = in_sizes[0] / 3;

    preprocess_kernel<<<(n + 63) / 64, 64>>>(pw, lowsh, highsh, rawop, sraw, rraw, Rcw, tcw, n);
    sort_scatter_kernel<<<(n + 63) / 64, 64>>>(n);
    bin_kernel<<<NTILES, 256>>>(n);
    render_kernel<<<dim3(TILES_X, TILES_Y), CHUNK>>>((float*)d_out);
}

// round 5
// speedup vs baseline: 3.0058x; 1.5024x over previous
#include <cuda_runtime.h>

#define MAXN 4096
#define IMG_W 128
#define IMG_H 128
#define TILE 8
#define TILES_X (IMG_W / TILE)
#define TILES_Y (IMG_H / TILE)
#define NTILES (TILES_X * TILES_Y)
#define SPLITK 4
#define GRIDSZ (NTILES * SPLITK)      // 1024 blocks
#define BLKT 64
#define FXc 300.0f
#define FYc 300.0f
#define LOG2E 1.4426950408889634f

// ---- scratch (allocation-free per harness rules) ----
__device__ float  g_z[MAXN];
__device__ int    g_rank[MAXN];
__device__ float4 g_a[MAXN], g_b[MAXN];
__device__ float2 g_c[MAXN];
__device__ float4 s_a[MAXN], s_b[MAXN];
__device__ float2 s_c[MAXN];
__device__ float4 g_part[SPLITK * NTILES * BLKT];   // (r,g,b,T) per pixel per segment
__device__ unsigned int g_barc[8];                  // monotonic barrier counters

__device__ __constant__ float C0 = 0.28209479177387814f;
__device__ __constant__ float C1 = 0.4886025119029199f;
__device__ __constant__ float C2_[5] = {1.0925484305920792f, -1.0925484305920792f,
                                        0.31539156525252005f, -1.0925484305920792f,
                                        0.5462742152960396f};
__device__ __constant__ float C3_[7] = {-0.5900435899266435f, 2.890611442640554f,
                                        -0.4570457994644658f, 0.3731763325901154f,
                                        -0.4570457994644658f, 1.445305721320277f,
                                        -0.5900435899266435f};

// Monotonic-counter global barrier: replay-safe (counters only grow; each launch
// advances each counter by exactly GRIDSZ). All GRIDSZ blocks are co-resident
// (launch_bounds(64,8) guarantees >=8 blocks/SM * 148 SMs > 1024).
__device__ __forceinline__ void global_barrier(int id) {
    __syncthreads();
    __threadfence();
    if (threadIdx.x == 0) {
        unsigned int old = atomicAdd(&g_barc[id], 1u);
        unsigned int target = (old / GRIDSZ + 1u) * GRIDSZ;
        while (*((volatile unsigned int*)&g_barc[id]) < target) { __nanosleep(64); }
        __threadfence();
    }
    __syncthreads();
}

__global__ void __launch_bounds__(BLKT, 8) fused_kernel(
        const float* __restrict__ pw,
        const float* __restrict__ lowsh,
        const float* __restrict__ highsh,
        const float* __restrict__ rawop,
        const float* __restrict__ sraw,
        const float* __restrict__ rraw,
        const float* __restrict__ Rcw,
        const float* __restrict__ tcw,
        float* __restrict__ out,
        int n) {
    int t   = threadIdx.x;
    int blk = blockIdx.x;
    int gid = blk * BLKT + t;

    // ---------------- Phase A: preprocess ----------------
    if (gid < n) {
        int i = gid;
        g_rank[i] = 0;

        float R00=Rcw[0],R01=Rcw[1],R02=Rcw[2];
        float R10=Rcw[3],R11=Rcw[4],R12=Rcw[5];
        float R20=Rcw[6],R21=Rcw[7],R22=Rcw[8];
        float t0=tcw[0], t1=tcw[1], t2=tcw[2];

        float px = pw[i*3+0], py = pw[i*3+1], pz = pw[i*3+2];

        float pc0 = R00*px + R01*py + R02*pz + t0;
        float pc1 = R10*px + R11*py + R12*pz + t1;
        float pc2 = R20*px + R21*py + R22*pz + t2;
        float invz = 1.0f / pc2;
        float u = FXc * pc0 * invz + 0.5f * IMG_W;
        float v = FYc * pc1 * invz + 0.5f * IMG_H;

        float op = 1.0f / (1.0f + expf(-rawop[i]));

        float s0 = expf(sraw[i*3+0]);
        float s1 = expf(sraw[i*3+1]);
        float s2 = expf(sraw[i*3+2]);

        float qw = rraw[i*4+0], qx = rraw[i*4+1], qy = rraw[i*4+2], qz = rraw[i*4+3];
        float qn = rsqrtf(qw*qw + qx*qx + qy*qy + qz*qz);
        qw *= qn; qx *= qn; qy *= qn; qz *= qn;

        float Rg00 = 1.0f - 2.0f*(qy*qy + qz*qz);
        float Rg01 = 2.0f*(qx*qy - qw*qz);
        float Rg02 = 2.0f*(qx*qz + qw*qy);
        float Rg10 = 2.0f*(qx*qy + qw*qz);
        float Rg11 = 1.0f - 2.0f*(qx*qx + qz*qz);
        float Rg12 = 2.0f*(qy*qz - qw*qx);
        float Rg20 = 2.0f*(qx*qz - qw*qy);
        float Rg21 = 2.0f*(qy*qz + qw*qx);
        float Rg22 = 1.0f - 2.0f*(qx*qx + qy*qy);

        float M00 = Rg00*s0, M01 = Rg01*s1, M02 = Rg02*s2;
        float M10 = Rg10*s0, M11 = Rg11*s1, M12 = Rg12*s2;
        float M20 = Rg20*s0, M21 = Rg21*s1, M22 = Rg22*s2;

        float j00 = FXc*invz, j02 = -FXc*pc0*invz*invz;
        float j11 = FYc*invz, j12 = -FYc*pc1*invz*invz;
        float T00 = j00*R00 + j02*R20;
        float T01 = j00*R01 + j02*R21;
        float T02 = j00*R02 + j02*R22;
        float T10 = j11*R10 + j12*R20;
        float T11 = j11*R11 + j12*R21;
        float T12 = j11*R12 + j12*R22;

        float V00 = T00*M00 + T01*M10 + T02*M20;
        float V01 = T00*M01 + T01*M11 + T02*M21;
        float V02 = T00*M02 + T01*M12 + T02*M22;
        float V10 = T10*M00 + T11*M10 + T12*M20;
        float V11 = T10*M01 + T11*M11 + T12*M21;
        float V12 = T10*M02 + T11*M12 + T12*M22;

        float a  = V00*V00 + V01*V01 + V02*V02 + 0.3f;
        float b  = V00*V10 + V01*V11 + V02*V12;
        float cc = V10*V10 + V11*V11 + V12*V12 + 0.3f;
        float det = a*cc - b*b;
        float ia =  cc / det;
        float ib = -b  / det;
        float ic =  a  / det;

        float dx0 = px + (R00*t0 + R10*t1 + R20*t2);
        float dy0 = py + (R01*t0 + R11*t1 + R21*t2);
        float dz0 = pz + (R02*t0 + R12*t1 + R22*t2);
        float dn = rsqrtf(dx0*dx0 + dy0*dy0 + dz0*dz0);
        float x = dx0*dn, y = dy0*dn, z = dz0*dn;

        float xx = x*x, yy = y*y, zz = z*z;
        float xy = x*y, yz = y*z, xz = x*z;

        float b1m = -C1*y, b1z = C1*z, b1x = -C1*x;
        float b4 = C2_[0]*xy;
        float b5 = C2_[1]*yz;
        float b6 = C2_[2]*(2.0f*zz - xx - yy);
        float b7 = C2_[3]*xz;
        float b8 = C2_[4]*(xx - yy);
        float b9  = C3_[0]*y*(3.0f*xx - yy);
        float b10 = C3_[1]*xy*z;
        float b11 = C3_[2]*y*(4.0f*zz - xx - yy);
        float b12 = C3_[3]*z*(2.0f*zz - 3.0f*xx - 3.0f*yy);
        float b13 = C3_[4]*x*(4.0f*zz - xx - yy);
        float b14 = C3_[5]*z*(xx - yy);
        float b15 = C3_[6]*x*(xx - 3.0f*yy);

        float col[3];
        const float* hs = highsh + i*45;
        #pragma unroll
        for (int ch = 0; ch < 3; ch++) {
            float res = C0 * lowsh[i*3+ch];
            res += b1m * hs[0*3+ch] + b1z * hs[1*3+ch] + b1x * hs[2*3+ch];
            res += b4  * hs[3*3+ch] + b5  * hs[4*3+ch] + b6  * hs[5*3+ch]
                 + b7  * hs[6*3+ch] + b8  * hs[7*3+ch];
            res += b9  * hs[8*3+ch] + b10 * hs[9*3+ch] + b11 * hs[10*3+ch]
                 + b12 * hs[11*3+ch] + b13 * hs[12*3+ch] + b14 * hs[13*3+ch]
                 + b15 * hs[14*3+ch];
            col[ch] = fmaxf(res + 0.5f, 0.0f);
        }

        float op_eff = (pc2 > 0.2f) ? op : 0.0f;

        float A2  = -0.5f * ia * LOG2E;
        float B2  = -ib * LOG2E;
        float Cc2 = -0.5f * ic * LOG2E;

        float mid  = 0.5f * (a + cc);
        float disc = sqrtf(0.25f * (a - cc) * (a - cc) + b * b);
        float lmax = mid + disc;
        float t255 = 255.0f * op_eff;
        float r2 = (t255 > 1.0f) ? 2.0f * logf(t255) * lmax * 1.0002f : -1.0f;

        g_z[i] = pc2;
        g_a[i] = make_float4(u, v, A2, B2);
        g_b[i] = make_float4(Cc2, op_eff, col[0], col[1]);
        g_c[i] = make_float2(col[2], r2);
    }

    global_barrier(0);

    // ---------------- Phase B1: distributed stable rank ----------------
    {
        int NS = (GRIDSZ * BLKT) / n;            // slices per gaussian (32 for n=2048)
        if (NS < 1) NS = 1;
        if (gid < n * NS) {
            int i     = gid % n;
            int slice = gid / n;
            int JL = (n + NS - 1) / NS;
            int j0 = slice * JL;
            int j1 = min(n, j0 + JL);
            float zi = g_z[i];
            int r = 0;
            for (int j = j0; j < j1; j++) {
                float zj = g_z[j];
                r += (zj < zi) || (zj == zi && j < i);
            }
            if (r) atomicAdd(&g_rank[i], r);
        }
    }

    global_barrier(1);

    // ---------------- Phase B2: scatter into depth order ----------------
    if (gid < n) {
        int r = g_rank[gid];
        s_a[r] = g_a[gid];
        s_b[r] = g_b[gid];
        s_c[r] = g_c[gid];
    }

    global_barrier(2);

    // ---------------- Phase C: fused cull + blend (split-K) ----------------
    {
        __shared__ unsigned short slist[(MAXN + SPLITK - 1) / SPLITK];
        __shared__ int wcnt[2];
        __shared__ float4 ca[BLKT], cb[BLKT];
        __shared__ float  ccb[BLKT];

        int tile = blk & (NTILES - 1);
        int seg  = blk >> 8;                 // NTILES == 256
        int tlx = tile & (TILES_X - 1);
        int tly = tile >> 4;                 // TILES_X == 16

        float xlo = tlx * TILE + 0.5f, xhi = tlx * TILE + (TILE - 0.5f);
        float ylo = tly * TILE + 0.5f, yhi = tly * TILE + (TILE - 0.5f);

        int SEGLEN = (n + SPLITK - 1) / SPLITK;
        int sbeg = seg * SEGLEN;
        int send = min(n, sbeg + SEGLEN);

        int wid = t >> 5, lid = t & 31;
        unsigned lmask = (1u << lid) - 1u;

        // cull + order-preserving compaction of this depth segment
        int cnt = 0;
        for (int c = sbeg; c < send; c += BLKT) {
            int i = c + t;
            int pred = 0;
            if (i < send) {
                float4 A = s_a[i];
                float r2 = s_c[i].y;
                float cu = fminf(fmaxf(A.x, xlo), xhi);
                float cv = fminf(fmaxf(A.y, ylo), yhi);
                float ddx = A.x - cu, ddy = A.y - cv;
                pred = (ddx * ddx + ddy * ddy <= r2) ? 1 : 0;
            }
            unsigned m = __ballot_sync(0xffffffffu, pred);
            if (lid == 0) wcnt[wid] = __popc(m);
            __syncthreads();
            int off = cnt + ((wid == 1) ? wcnt[0] : 0) + __popc(m & lmask);
            if (pred) slist[off] = (unsigned short)i;
            int tot = wcnt[0] + wcnt[1];
            __syncthreads();
            cnt += tot;
        }

        float pxf = tlx * TILE + (t & 7) + 0.5f;
        float pyf = tly * TILE + (t >> 3) + 0.5f;

        float T = 1.0f, cr = 0.0f, cg = 0.0f, cbl = 0.0f;

        for (int base = 0; base < cnt; base += BLKT) {
            if (__syncthreads_and(T < 1e-5f)) break;
            if (base + t < cnt) {
                int idx = slist[base + t];
                ca[t]  = s_a[idx];
                cb[t]  = s_b[idx];
                ccb[t] = s_c[idx].x;
            }
            __syncthreads();
            int m = min(BLKT, cnt - base);
            #pragma unroll 4
            for (int k = 0; k < m; k++) {
                float4 A = ca[k];
                float4 B = cb[k];
                float dx = A.x - pxf;
                float dy = A.y - pyf;
                float p = A.z * dx * dx;
                p = fmaf(B.x, dy * dy, p);
                p = fmaf(A.w, dx * dy, p);
                p = fminf(p, 0.0f);
                float gw;
                asm("ex2.approx.f32 %0, %1;" : "=f"(gw) : "f"(p));
                float alpha = fminf(0.99f, B.y * gw);
                alpha = (alpha >= (1.0f / 255.0f)) ? alpha : 0.0f;
                float w = T * alpha;
                cr  = fmaf(w, B.z, cr);
                cg  = fmaf(w, B.w, cg);
                cbl = fmaf(w, ccb[k], cbl);
                T = fmaf(-alpha, T, T);
            }
        }

        g_part[(seg * NTILES + tile) * BLKT + t] = make_float4(cr, cg, cbl, T);
    }

    global_barrier(3);

    // ---------------- Phase D: compose segments front-to-back ----------------
    if (blk < NTILES) {
        int tile = blk;
        int tlx = tile & (TILES_X - 1);
        int tly = tile >> 4;
        float T = 1.0f, cr = 0.0f, cg = 0.0f, cbl = 0.0f;
        #pragma unroll
        for (int s = 0; s < SPLITK; s++) {
            float4 P = g_part[(s * NTILES + tile) * BLKT + t];
            cr  = fmaf(T, P.x, cr);
            cg  = fmaf(T, P.y, cg);
            cbl = fmaf(T, P.z, cbl);
            T *= P.w;
        }
        int pxi = tlx * TILE + (t & 7);
        int pyi = tly * TILE + (t >> 3);
        int o = (pyi * IMG_W + pxi) * 3;
        out[o + 0] = cr;
        out[o + 1] = cg;
        out[o + 2] = cbl;
    }
}

extern "C" void kernel_launch(void* const* d_in, const int* in_sizes, int n_in,
                              void* d_out, int out_size) {
    const float* pw     = (const float*)d_in[0];
    const float* lowsh  = (const float*)d_in[1];
    const float* highsh = (const float*)d_in[2];
    const float* rawop  = (const float*)d_in[3];
    const float* sraw   = (const float*)d_in[4];
    const float* rraw   = (const float*)d_in[5];
    const float* Rcw    = (const float*)d_in[6];
    const float* tcw    = (const float*)d_in[7];
    int n = in_sizes[0] / 3;

    fused_kernel<<<GRIDSZ, BLKT>>>(pw, lowsh, highsh, rawop, sraw, rraw, Rcw, tcw,
                                   (float*)d_out, n);
}

// round 6
// speedup vs baseline: 3.0088x; 1.0010x over previous
#include <cuda_runtime.h>

#define MAXN 4096
#define IMG_W 128
#define IMG_H 128
#define TILE 8
#define TILES_X (IMG_W / TILE)
#define TILES_Y (IMG_H / TILE)
#define NTILES (TILES_X * TILES_Y)
#define SPLITK 4
#define GRIDSZ (NTILES * SPLITK)      // 1024 blocks
#define BLKT 64
#define FXc 300.0f
#define FYc 300.0f
#define LOG2E 1.4426950408889634f

// ---- scratch (allocation-free per harness rules) ----
__device__ float  g_z[MAXN];
__device__ int    g_rank[MAXN];
__device__ float4 g_a[MAXN];                 // (u, v, A2, B2)        [geom]
__device__ float4 g_d[MAXN];                 // (Cc2, op_eff, r2, z)  [geom]
__device__ float  g_colv[3 * MAXN];          // rgb                   [color]
__device__ float4 s_a[MAXN], s_b[MAXN];      // depth-sorted payload
__device__ float2 s_c[MAXN];
__device__ float4 g_part[SPLITK * NTILES * BLKT];   // (r,g,b,T)
__device__ unsigned int g_barc[8];                  // monotonic barrier counters

__device__ __constant__ float C0 = 0.28209479177387814f;
__device__ __constant__ float C1 = 0.4886025119029199f;
__device__ __constant__ float C2_[5] = {1.0925484305920792f, -1.0925484305920792f,
                                        0.31539156525252005f, -1.0925484305920792f,
                                        0.5462742152960396f};
__device__ __constant__ float C3_[7] = {-0.5900435899266435f, 2.890611442640554f,
                                        -0.4570457994644658f, 0.3731763325901154f,
                                        -0.4570457994644658f, 1.445305721320277f,
                                        -0.5900435899266435f};

// Monotonic-counter global barrier: replay-safe (counters only grow; each launch
// advances each counter by exactly GRIDSZ). All GRIDSZ blocks co-resident
// (launch_bounds(64,8): 8 blocks/SM * 148 SMs > 1024).
__device__ __forceinline__ void global_barrier(int id) {
    __syncthreads();
    __threadfence();
    if (threadIdx.x == 0) {
        unsigned int old = atomicAdd(&g_barc[id], 1u);
        unsigned int target = (old / GRIDSZ + 1u) * GRIDSZ;
        while (*((volatile unsigned int*)&g_barc[id]) < target) { __nanosleep(32); }
        __threadfence();
    }
    __syncthreads();
}

__global__ void __launch_bounds__(BLKT, 8) fused_kernel(
        const float* __restrict__ pw,
        const float* __restrict__ lowsh,
        const float* __restrict__ highsh,
        const float* __restrict__ rawop,
        const float* __restrict__ sraw,
        const float* __restrict__ rraw,
        const float* __restrict__ Rcw,
        const float* __restrict__ tcw,
        float* __restrict__ out,
        int n) {
    int t   = threadIdx.x;
    int blk = blockIdx.x;
    int gid = blk * BLKT + t;

    int geomBlocks = (n + BLKT - 1) / BLKT;

    // ---------------- Phase A (parallel tasks on disjoint blocks) ----------------
    if (gid < n) {
        // ---- A-geom: projection, covariance, cull radius ----
        int i = gid;
        g_rank[i] = 0;

        float R00=Rcw[0],R01=Rcw[1],R02=Rcw[2];
        float R10=Rcw[3],R11=Rcw[4],R12=Rcw[5];
        float R20=Rcw[6],R21=Rcw[7],R22=Rcw[8];
        float t0=tcw[0], t1=tcw[1], t2=tcw[2];

        float px = pw[i*3+0], py = pw[i*3+1], pz = pw[i*3+2];

        float pc0 = R00*px + R01*py + R02*pz + t0;
        float pc1 = R10*px + R11*py + R12*pz + t1;
        float pc2 = R20*px + R21*py + R22*pz + t2;
        float invz = 1.0f / pc2;
        float u = FXc * pc0 * invz + 0.5f * IMG_W;
        float v = FYc * pc1 * invz + 0.5f * IMG_H;

        float op = 1.0f / (1.0f + __expf(-rawop[i]));

        float s0 = __expf(sraw[i*3+0]);
        float s1 = __expf(sraw[i*3+1]);
        float s2 = __expf(sraw[i*3+2]);

        float qw = rraw[i*4+0], qx = rraw[i*4+1], qy = rraw[i*4+2], qz = rraw[i*4+3];
        float qn = rsqrtf(qw*qw + qx*qx + qy*qy + qz*qz);
        qw *= qn; qx *= qn; qy *= qn; qz *= qn;

        float Rg00 = 1.0f - 2.0f*(qy*qy + qz*qz);
        float Rg01 = 2.0f*(qx*qy - qw*qz);
        float Rg02 = 2.0f*(qx*qz + qw*qy);
        float Rg10 = 2.0f*(qx*qy + qw*qz);
        float Rg11 = 1.0f - 2.0f*(qx*qx + qz*qz);
        float Rg12 = 2.0f*(qy*qz - qw*qx);
        float Rg20 = 2.0f*(qx*qz - qw*qy);
        float Rg21 = 2.0f*(qy*qz + qw*qx);
        float Rg22 = 1.0f - 2.0f*(qx*qx + qy*qy);

        float M00 = Rg00*s0, M01 = Rg01*s1, M02 = Rg02*s2;
        float M10 = Rg10*s0, M11 = Rg11*s1, M12 = Rg12*s2;
        float M20 = Rg20*s0, M21 = Rg21*s1, M22 = Rg22*s2;

        float j00 = FXc*invz, j02 = -FXc*pc0*invz*invz;
        float j11 = FYc*invz, j12 = -FYc*pc1*invz*invz;
        float T00 = j00*R00 + j02*R20;
        float T01 = j00*R01 + j02*R21;
        float T02 = j00*R02 + j02*R22;
        float T10 = j11*R10 + j12*R20;
        float T11 = j11*R11 + j12*R21;
        float T12 = j11*R12 + j12*R22;

        float V00 = T00*M00 + T01*M10 + T02*M20;
        float V01 = T00*M01 + T01*M11 + T02*M21;
        float V02 = T00*M02 + T01*M12 + T02*M22;
        float V10 = T10*M00 + T11*M10 + T12*M20;
        float V11 = T10*M01 + T11*M11 + T12*M21;
        float V12 = T10*M02 + T11*M12 + T12*M22;

        float a  = V00*V00 + V01*V01 + V02*V02 + 0.3f;
        float b  = V00*V10 + V01*V11 + V02*V12;
        float cc = V10*V10 + V11*V11 + V12*V12 + 0.3f;
        float det = a*cc - b*b;
        float idet = 1.0f / det;
        float ia =  cc * idet;
        float ib = -b  * idet;
        float ic =  a  * idet;

        float op_eff = (pc2 > 0.2f) ? op : 0.0f;

        float A2  = -0.5f * ia * LOG2E;
        float B2  = -ib * LOG2E;
        float Cc2 = -0.5f * ic * LOG2E;

        float mid  = 0.5f * (a + cc);
        float disc = sqrtf(0.25f * (a - cc) * (a - cc) + b * b);
        float lmax = mid + disc;
        float t255 = 255.0f * op_eff;
        float r2 = (t255 > 1.0f) ? 2.0f * __logf(t255) * lmax * 1.0002f : -1.0f;

        g_z[i] = pc2;
        g_a[i] = make_float4(u, v, A2, B2);
        g_d[i] = make_float4(Cc2, op_eff, r2, pc2);
    } else {
        // ---- A-color: SH -> rgb, 3 threads per gaussian (one channel each) ----
        int cid = gid - geomBlocks * BLKT;
        if (cid >= 0 && cid < 3 * n) {
            int i  = cid / 3;
            int ch = cid - 3 * i;

            float R00=Rcw[0],R01=Rcw[1],R02=Rcw[2];
            float R10=Rcw[3],R11=Rcw[4],R12=Rcw[5];
            float R20=Rcw[6],R21=Rcw[7],R22=Rcw[8];
            float t0=tcw[0], t1=tcw[1], t2=tcw[2];

            float px = pw[i*3+0], py = pw[i*3+1], pz = pw[i*3+2];

            float dx0 = px + (R00*t0 + R10*t1 + R20*t2);
            float dy0 = py + (R01*t0 + R11*t1 + R21*t2);
            float dz0 = pz + (R02*t0 + R12*t1 + R22*t2);
            float dn = rsqrtf(dx0*dx0 + dy0*dy0 + dz0*dz0);
            float x = dx0*dn, y = dy0*dn, z = dz0*dn;

            float xx = x*x, yy = y*y, zz = z*z;
            float xy = x*y, yz = y*z, xz = x*z;

            const float* hs = highsh + i*45 + ch;
            float res = C0 * lowsh[i*3+ch];
            res += (-C1*y) * hs[0*3] + (C1*z) * hs[1*3] + (-C1*x) * hs[2*3];
            res += (C2_[0]*xy) * hs[3*3] + (C2_[1]*yz) * hs[4*3]
                 + (C2_[2]*(2.0f*zz - xx - yy)) * hs[5*3]
                 + (C2_[3]*xz) * hs[6*3] + (C2_[4]*(xx - yy)) * hs[7*3];
            res += (C3_[0]*y*(3.0f*xx - yy)) * hs[8*3]
                 + (C3_[1]*xy*z) * hs[9*3]
                 + (C3_[2]*y*(4.0f*zz - xx - yy)) * hs[10*3]
                 + (C3_[3]*z*(2.0f*zz - 3.0f*xx - 3.0f*yy)) * hs[11*3]
                 + (C3_[4]*x*(4.0f*zz - xx - yy)) * hs[12*3]
                 + (C3_[5]*z*(xx - yy)) * hs[13*3]
                 + (C3_[6]*x*(xx - 3.0f*yy)) * hs[14*3];
            g_colv[i*3+ch] = fmaxf(res + 0.5f, 0.0f);
        }
    }

    global_barrier(0);

    // ---------------- Phase B1: distributed stable rank ----------------
    {
        int NS = (GRIDSZ * BLKT) / n;            // slices per gaussian
        if (NS < 1) NS = 1;
        if (gid < n * NS) {
            int i     = gid % n;
            int slice = gid / n;
            int JL = (n + NS - 1) / NS;
            int j0 = slice * JL;
            int j1 = min(n, j0 + JL);
            float zi = g_z[i];
            int r = 0;
            for (int j = j0; j < j1; j++) {
                float zj = g_z[j];
                r += (zj < zi) || (zj == zi && j < i);
            }
            if (r) atomicAdd(&g_rank[i], r);
        }
    }

    global_barrier(1);

    // ---------------- Phase B2: scatter into depth order ----------------
    if (gid < n) {
        int r = g_rank[gid];
        float4 d = g_d[gid];
        s_a[r] = g_a[gid];
        s_b[r] = make_float4(d.x, d.y, g_colv[gid*3+0], g_colv[gid*3+1]);
        s_c[r] = make_float2(g_colv[gid*3+2], d.z);   // (colB, r2)
    }

    global_barrier(2);

    // ---------------- Phase C: fused cull + blend (split-K) ----------------
    {
        __shared__ unsigned short slist[(MAXN + SPLITK - 1) / SPLITK];
        __shared__ int wcnt[2];
        __shared__ float4 ca[BLKT], cb[BLKT];
        __shared__ float  ccb[BLKT];

        int tile = blk & (NTILES - 1);
        int seg  = blk >> 8;                 // NTILES == 256
        int tlx = tile & (TILES_X - 1);
        int tly = tile >> 4;                 // TILES_X == 16

        float xlo = tlx * TILE + 0.5f, xhi = tlx * TILE + (TILE - 0.5f);
        float ylo = tly * TILE + 0.5f, yhi = tly * TILE + (TILE - 0.5f);

        int SEGLEN = (n + SPLITK - 1) / SPLITK;
        int sbeg = seg * SEGLEN;
        int send = min(n, sbeg + SEGLEN);

        int wid = t >> 5, lid = t & 31;
        unsigned lmask = (1u << lid) - 1u;

        int cnt = 0;
        for (int c = sbeg; c < send; c += BLKT) {
            int i = c + t;
            int pred = 0;
            if (i < send) {
                float4 A = s_a[i];
                float r2 = s_c[i].y;
                float cu = fminf(fmaxf(A.x, xlo), xhi);
                float cv = fminf(fmaxf(A.y, ylo), yhi);
                float ddx = A.x - cu, ddy = A.y - cv;
                pred = (ddx * ddx + ddy * ddy <= r2) ? 1 : 0;
            }
            unsigned m = __ballot_sync(0xffffffffu, pred);
            if (lid == 0) wcnt[wid] = __popc(m);
            __syncthreads();
            int off = cnt + ((wid == 1) ? wcnt[0] : 0) + __popc(m & lmask);
            if (pred) slist[off] = (unsigned short)i;
            int tot = wcnt[0] + wcnt[1];
            __syncthreads();
            cnt += tot;
        }

        float pxf = tlx * TILE + (t & 7) + 0.5f;
        float pyf = tly * TILE + (t >> 3) + 0.5f;

        float T = 1.0f, cr = 0.0f, cg = 0.0f, cbl = 0.0f;

        for (int base = 0; base < cnt; base += BLKT) {
            if (__syncthreads_and(T < 1e-5f)) break;
            if (base + t < cnt) {
                int idx = slist[base + t];
                ca[t]  = s_a[idx];
                cb[t]  = s_b[idx];
                ccb[t] = s_c[idx].x;
            }
            __syncthreads();
            int m = min(BLKT, cnt - base);
            #pragma unroll 4
            for (int k = 0; k < m; k++) {
                float4 A = ca[k];
                float4 B = cb[k];
                float dx = A.x - pxf;
                float dy = A.y - pyf;
                float p = A.z * dx * dx;
                p = fmaf(B.x, dy * dy, p);
                p = fmaf(A.w, dx * dy, p);
                p = fminf(p, 0.0f);
                float gw;
                asm("ex2.approx.f32 %0, %1;" : "=f"(gw) : "f"(p));
                float alpha = fminf(0.99f, B.y * gw);
                alpha = (alpha >= (1.0f / 255.0f)) ? alpha : 0.0f;
                float w = T * alpha;
                cr  = fmaf(w, B.z, cr);
                cg  = fmaf(w, B.w, cg);
                cbl = fmaf(w, ccb[k], cbl);
                T = fmaf(-alpha, T, T);
            }
        }

        g_part[(seg * NTILES + tile) * BLKT + t] = make_float4(cr, cg, cbl, T);
    }

    global_barrier(3);

    // ---------------- Phase D: compose segments front-to-back ----------------
    if (blk < NTILES) {
        int tile = blk;
        int tlx = tile & (TILES_X - 1);
        int tly = tile >> 4;
        float T = 1.0f, cr = 0.0f, cg = 0.0f, cbl = 0.0f;
        #pragma unroll
        for (int s = 0; s < SPLITK; s++) {
            float4 P = g_part[(s * NTILES + tile) * BLKT + t];
            cr  = fmaf(T, P.x, cr);
            cg  = fmaf(T, P.y, cg);
            cbl = fmaf(T, P.z, cbl);
            T *= P.w;
        }
        int pxi = tlx * TILE + (t & 7);
        int pyi = tly * TILE + (t >> 3);
        int o = (pyi * IMG_W + pxi) * 3;
        out[o + 0] = cr;
        out[o + 1] = cg;
        out[o + 2] = cbl;
    }
}

extern "C" void kernel_launch(void* const* d_in, const int* in_sizes, int n_in,
                              void* d_out, int out_size) {
    const float* pw     = (const float*)d_in[0];
    const float* lowsh  = (const float*)d_in[1];
    const float* highsh = (const float*)d_in[2];
    const float* rawop  = (const float*)d_in[3];
    const float* sraw   = (const float*)d_in[4];
    const float* rraw   = (const float*)d_in[5];
    const float* Rcw    = (const float*)d_in[6];
    const float* tcw    = (const float*)d_in[7];
    int n = in_sizes[0] / 3;

    fused_kernel<<<GRIDSZ, BLKT>>>(pw, lowsh, highsh, rawop, sraw, rraw, Rcw, tcw,
                                   (float*)d_out, n);
}

// round 7
// speedup vs baseline: 4.3872x; 1.4582x over previous
#include <cuda_runtime.h>

#define MAXN 4096
#define IMG_W 128
#define IMG_H 128
#define TILE 8
#define TILES_X 16
#define TILES_Y 16
#define NTILES 256
#define GRID2 256
#define BLK2 256
#define FXc 300.0f
#define FYc 300.0f
#define LOG2E 1.4426950408889634f
#define MAXLIST 2048

// ---- scratch (allocation-free per harness rules) ----
__device__ float  g_z[MAXN];
__device__ int    g_rank[MAXN];
__device__ float4 g_a[MAXN];                 // (u, v, A2, B2)        [geom]
__device__ float4 g_d[MAXN];                 // (Cc2, op_eff, r2, z)  [geom]
__device__ float  g_colv[3 * MAXN];          // rgb                   [color]
__device__ float4 s_a[MAXN], s_b[MAXN];      // depth-sorted payload
__device__ float2 s_c[MAXN];
__device__ unsigned int g_leaf[3][8];        // monotonic two-level barrier
__device__ unsigned int g_root[3];

__device__ __constant__ float C0 = 0.28209479177387814f;
__device__ __constant__ float C1 = 0.4886025119029199f;
__device__ __constant__ float C2_[5] = {1.0925484305920792f, -1.0925484305920792f,
                                        0.31539156525252005f, -1.0925484305920792f,
                                        0.5462742152960396f};
__device__ __constant__ float C3_[7] = {-0.5900435899266435f, 2.890611442640554f,
                                        -0.4570457994644658f, 0.3731763325901154f,
                                        -0.4570457994644658f, 1.445305721320277f,
                                        -0.5900435899266435f};

// Two-level monotonic barrier, replay-safe. 256 blocks: leaf = blk&7 gets 32
// arrivals/round (spread over 8 L2 slots); last arrival of each leaf round
// bumps root by 1 (8/round). Waiters poll root only.
__device__ __forceinline__ void gbar(int id) {
    __syncthreads();
    __threadfence();
    if (threadIdx.x == 0) {
        int leaf = blockIdx.x & 7;
        unsigned int old = atomicAdd(&g_leaf[id][leaf], 1u);
        if ((old & 31u) == 31u) atomicAdd(&g_root[id], 1u);
        unsigned int target = ((old >> 5) + 1u) * 8u;
        while (*((volatile unsigned int*)&g_root[id]) < target) { __nanosleep(32); }
        __threadfence();
    }
    __syncthreads();
}

__global__ void __launch_bounds__(BLK2, 2) fused_kernel(
        const float* __restrict__ pw,
        const float* __restrict__ lowsh,
        const float* __restrict__ highsh,
        const float* __restrict__ rawop,
        const float* __restrict__ sraw,
        const float* __restrict__ rraw,
        const float* __restrict__ Rcw,
        const float* __restrict__ tcw,
        float* __restrict__ out,
        int n) {
    int t   = threadIdx.x;
    int blk = blockIdx.x;
    int gid = blk * BLK2 + t;

    // ---------------- Phase A0: z only (cheap) + zero ranks ----------------
    if (gid < n) {
        float px = pw[gid*3+0], py = pw[gid*3+1], pz = pw[gid*3+2];
        g_z[gid] = Rcw[6]*px + Rcw[7]*py + Rcw[8]*pz + tcw[2];
        g_rank[gid] = 0;
    }

    gbar(0);

    // ---------------- Phase A1: rank || geom || color (disjoint threads) ----
    {
        int total = GRID2 * BLK2;
        int NS = total / n - 4;           // rank slices per gaussian
        if (NS < 1) NS = 1;
        int rankEnd = n * NS;
        int JL = (n + NS - 1) / NS;

        if (gid < rankEnd) {
            // ---- distributed stable rank ----
            int i     = gid % n;
            int slice = gid / n;
            int j0 = slice * JL;
            int j1 = min(n, j0 + JL);
            float zi = g_z[i];
            int r = 0;
            for (int j = j0; j < j1; j++) {
                float zj = g_z[j];
                r += (zj < zi) || (zj == zi && j < i);
            }
            if (r) atomicAdd(&g_rank[i], r);
        } else if (gid < rankEnd + n) {
            // ---- geom: projection, covariance, cull radius ----
            int i = gid - rankEnd;

            float R00=Rcw[0],R01=Rcw[1],R02=Rcw[2];
            float R10=Rcw[3],R11=Rcw[4],R12=Rcw[5];
            float R20=Rcw[6],R21=Rcw[7],R22=Rcw[8];
            float t0=tcw[0], t1=tcw[1], t2=tcw[2];

            float px = pw[i*3+0], py = pw[i*3+1], pz = pw[i*3+2];

            float pc0 = R00*px + R01*py + R02*pz + t0;
            float pc1 = R10*px + R11*py + R12*pz + t1;
            float pc2 = R20*px + R21*py + R22*pz + t2;
            float invz = 1.0f / pc2;
            float u = FXc * pc0 * invz + 0.5f * IMG_W;
            float v = FYc * pc1 * invz + 0.5f * IMG_H;

            float op = 1.0f / (1.0f + __expf(-rawop[i]));

            float s0 = __expf(sraw[i*3+0]);
            float s1 = __expf(sraw[i*3+1]);
            float s2 = __expf(sraw[i*3+2]);

            float qw = rraw[i*4+0], qx = rraw[i*4+1], qy = rraw[i*4+2], qz = rraw[i*4+3];
            float qn = rsqrtf(qw*qw + qx*qx + qy*qy + qz*qz);
            qw *= qn; qx *= qn; qy *= qn; qz *= qn;

            float Rg00 = 1.0f - 2.0f*(qy*qy + qz*qz);
            float Rg01 = 2.0f*(qx*qy - qw*qz);
            float Rg02 = 2.0f*(qx*qz + qw*qy);
            float Rg10 = 2.0f*(qx*qy + qw*qz);
            float Rg11 = 1.0f - 2.0f*(qx*qx + qz*qz);
            float Rg12 = 2.0f*(qy*qz - qw*qx);
            float Rg20 = 2.0f*(qx*qz - qw*qy);
            float Rg21 = 2.0f*(qy*qz + qw*qx);
            float Rg22 = 1.0f - 2.0f*(qx*qx + qy*qy);

            float M00 = Rg00*s0, M01 = Rg01*s1, M02 = Rg02*s2;
            float M10 = Rg10*s0, M11 = Rg11*s1, M12 = Rg12*s2;
            float M20 = Rg20*s0, M21 = Rg21*s1, M22 = Rg22*s2;

            float j00 = FXc*invz, j02 = -FXc*pc0*invz*invz;
            float j11 = FYc*invz, j12 = -FYc*pc1*invz*invz;
            float T00 = j00*R00 + j02*R20;
            float T01 = j00*R01 + j02*R21;
            float T02 = j00*R02 + j02*R22;
            float T10 = j11*R10 + j12*R20;
            float T11 = j11*R11 + j12*R21;
            float T12 = j11*R12 + j12*R22;

            float V00 = T00*M00 + T01*M10 + T02*M20;
            float V01 = T00*M01 + T01*M11 + T02*M21;
            float V02 = T00*M02 + T01*M12 + T02*M22;
            float V10 = T10*M00 + T11*M10 + T12*M20;
            float V11 = T10*M01 + T11*M11 + T12*M21;
            float V12 = T10*M02 + T11*M12 + T12*M22;

            float a  = V00*V00 + V01*V01 + V02*V02 + 0.3f;
            float b  = V00*V10 + V01*V11 + V02*V12;
            float cc = V10*V10 + V11*V11 + V12*V12 + 0.3f;
            float det = a*cc - b*b;
            float idet = 1.0f / det;
            float ia =  cc * idet;
            float ib = -b  * idet;
            float ic =  a  * idet;

            float op_eff = (pc2 > 0.2f) ? op : 0.0f;

            float A2  = -0.5f * ia * LOG2E;
            float B2  = -ib * LOG2E;
            float Cc2 = -0.5f * ic * LOG2E;

            float mid  = 0.5f * (a + cc);
            float disc = sqrtf(0.25f * (a - cc) * (a - cc) + b * b);
            float lmax = mid + disc;
            float t255 = 255.0f * op_eff;
            float r2 = (t255 > 1.0f) ? 2.0f * __logf(t255) * lmax * 1.0002f : -1.0f;

            g_a[i] = make_float4(u, v, A2, B2);
            g_d[i] = make_float4(Cc2, op_eff, r2, pc2);
        } else if (gid < rankEnd + 4*n) {
            // ---- color: SH -> rgb, 3 threads per gaussian ----
            int cid = gid - rankEnd - n;
            int i  = cid / 3;
            int ch = cid - 3 * i;

            float R00=Rcw[0],R01=Rcw[1],R02=Rcw[2];
            float R10=Rcw[3],R11=Rcw[4],R12=Rcw[5];
            float R20=Rcw[6],R21=Rcw[7],R22=Rcw[8];
            float t0=tcw[0], t1=tcw[1], t2=tcw[2];

            float px = pw[i*3+0], py = pw[i*3+1], pz = pw[i*3+2];

            float dx0 = px + (R00*t0 + R10*t1 + R20*t2);
            float dy0 = py + (R01*t0 + R11*t1 + R21*t2);
            float dz0 = pz + (R02*t0 + R12*t1 + R22*t2);
            float dn = rsqrtf(dx0*dx0 + dy0*dy0 + dz0*dz0);
            float x = dx0*dn, y = dy0*dn, z = dz0*dn;

            float xx = x*x, yy = y*y, zz = z*z;
            float xy = x*y, yz = y*z, xz = x*z;

            const float* hs = highsh + i*45 + ch;
            float res = C0 * lowsh[i*3+ch];
            res += (-C1*y) * hs[0*3] + (C1*z) * hs[1*3] + (-C1*x) * hs[2*3];
            res += (C2_[0]*xy) * hs[3*3] + (C2_[1]*yz) * hs[4*3]
                 + (C2_[2]*(2.0f*zz - xx - yy)) * hs[5*3]
                 + (C2_[3]*xz) * hs[6*3] + (C2_[4]*(xx - yy)) * hs[7*3];
            res += (C3_[0]*y*(3.0f*xx - yy)) * hs[8*3]
                 + (C3_[1]*xy*z) * hs[9*3]
                 + (C3_[2]*y*(4.0f*zz - xx - yy)) * hs[10*3]
                 + (C3_[3]*z*(2.0f*zz - 3.0f*xx - 3.0f*yy)) * hs[11*3]
                 + (C3_[4]*x*(4.0f*zz - xx - yy)) * hs[12*3]
                 + (C3_[5]*z*(xx - yy)) * hs[13*3]
                 + (C3_[6]*x*(xx - 3.0f*yy)) * hs[14*3];
            g_colv[i*3+ch] = fmaxf(res + 0.5f, 0.0f);
        }
    }

    gbar(1);

    // ---------------- Phase B2: scatter into depth order ----------------
    if (gid < n) {
        int r = g_rank[gid];
        float4 d = g_d[gid];
        s_a[r] = g_a[gid];
        s_b[r] = make_float4(d.x, d.y, g_colv[gid*3+0], g_colv[gid*3+1]);
        s_c[r] = make_float2(g_colv[gid*3+2], d.z);   // (colB, r2)
    }

    gbar(2);

    // ---------------- Phase C: cull + in-block split-K blend + compose ------
    {
        __shared__ unsigned short slist[MAXLIST];
        __shared__ int wcnt[8];
        __shared__ float4 ca[4][64], cb[4][64];
        __shared__ float  ccb[4][64];
        __shared__ float4 part[4][64];

        int tlx = blk & (TILES_X - 1);
        int tly = blk >> 4;

        float xlo = tlx * TILE + 0.5f, xhi = tlx * TILE + (TILE - 0.5f);
        float ylo = tly * TILE + 0.5f, yhi = tly * TILE + (TILE - 0.5f);

        int wid = t >> 5, lid = t & 31;
        unsigned lmask = (1u << lid) - 1u;

        // cull all n gaussians (order-preserving 8-warp compaction)
        int cnt = 0;
        for (int c = 0; c < n; c += BLK2) {
            int i = c + t;
            int pred = 0;
            if (i < n) {
                float4 A = s_a[i];
                float r2 = s_c[i].y;
                float cu = fminf(fmaxf(A.x, xlo), xhi);
                float cv = fminf(fmaxf(A.y, ylo), yhi);
                float ddx = A.x - cu, ddy = A.y - cv;
                pred = (ddx * ddx + ddy * ddy <= r2) ? 1 : 0;
            }
            unsigned m = __ballot_sync(0xffffffffu, pred);
            if (lid == 0) wcnt[wid] = __popc(m);
            __syncthreads();
            int off = cnt + __popc(m & lmask);
            int tot = 0;
            #pragma unroll
            for (int w = 0; w < 8; w++) {
                int c8 = wcnt[w];
                if (w < wid) off += c8;
                tot += c8;
            }
            if (pred) slist[off] = (unsigned short)i;
            __syncthreads();
            cnt += tot;
        }

        // split-K across the culled list: quarter q of threads blends list
        // quarter q for all 64 pixels
        int q = t >> 6;
        int p = t & 63;
        float pxf = tlx * TILE + (p & 7) + 0.5f;
        float pyf = tly * TILE + (p >> 3) + 0.5f;

        int L4 = (cnt + 3) >> 2;
        int qbeg = q * L4;
        int qend = min(cnt, qbeg + L4);

        float T = 1.0f, cr = 0.0f, cg = 0.0f, cbl = 0.0f;

        for (int base = 0; base < L4; base += 64) {
            int src = qbeg + base + p;
            if (src < qend) {
                int idx = slist[src];
                ca[q][p]  = s_a[idx];
                cb[q][p]  = s_b[idx];
                ccb[q][p] = s_c[idx].x;
            }
            __syncthreads();
            int m = min(64, qend - (qbeg + base));
            #pragma unroll 4
            for (int k = 0; k < m; k++) {
                float4 A = ca[q][k];
                float4 B = cb[q][k];
                float dx = A.x - pxf;
                float dy = A.y - pyf;
                float pp = A.z * dx * dx;
                pp = fmaf(B.x, dy * dy, pp);
                pp = fmaf(A.w, dx * dy, pp);
                pp = fminf(pp, 0.0f);
                float gw;
                asm("ex2.approx.f32 %0, %1;" : "=f"(gw) : "f"(pp));
                float alpha = fminf(0.99f, B.y * gw);
                alpha = (alpha >= (1.0f / 255.0f)) ? alpha : 0.0f;
                float w = T * alpha;
                cr  = fmaf(w, B.z, cr);
                cg  = fmaf(w, B.w, cg);
                cbl = fmaf(w, ccb[q][k], cbl);
                T = fmaf(-alpha, T, T);
            }
            __syncthreads();
        }

        part[q][p] = make_float4(cr, cg, cbl, T);
        __syncthreads();

        // compose 4 quarters front-to-back (threads 0..63)
        if (t < 64) {
            float Tc = 1.0f, rr = 0.0f, gg = 0.0f, bb = 0.0f;
            #pragma unroll
            for (int s = 0; s < 4; s++) {
                float4 P = part[s][t];
                rr = fmaf(Tc, P.x, rr);
                gg = fmaf(Tc, P.y, gg);
                bb = fmaf(Tc, P.z, bb);
                Tc *= P.w;
            }
            int pxi = tlx * TILE + (t & 7);
            int pyi = tly * TILE + (t >> 3);
            int o = (pyi * IMG_W + pxi) * 3;
            out[o + 0] = rr;
            out[o + 1] = gg;
            out[o + 2] = bb;
        }
    }
}

extern "C" void kernel_launch(void* const* d_in, const int* in_sizes, int n_in,
                              void* d_out, int out_size) {
    const float* pw     = (const float*)d_in[0];
    const float* lowsh  = (const float*)d_in[1];
    const float* highsh = (const float*)d_in[2];
    const float* rawop  = (const float*)d_in[3];
    const float* sraw   = (const float*)d_in[4];
    const float* rraw   = (const float*)d_in[5];
    const float* Rcw    = (const float*)d_in[6];
    const float* tcw    = (const float*)d_in[7];
    int n = in_sizes[0] / 3;

    fused_kernel<<<GRID2, BLK2>>>(pw, lowsh, highsh, rawop, sraw, rraw, Rcw, tcw,
                                  (float*)d_out, n);
}